// round 17
// baseline (speedup 1.0000x reference)
#include <cuda_runtime.h>
#include <cuda_fp16.h>
#include <cstdint>
#include <cstddef>

#define WIN 7
#define NTOK 49
#define NH 16
#define HD 32
#define CDIM 512
#define BATCH 2048
#define M_TOT (BATCH * NTOK)   // 100352 = 784 * 128
#define KEFF 512

// ---------------- scratch (static device globals; no allocations) ----------------
__device__ __half g_x16  [(size_t)M_TOT * CDIM];
__device__ __half g_qkv16[(size_t)M_TOT * 3 * CDIM];
__device__ __half g_att16[(size_t)M_TOT * CDIM];
__device__ __half g_W16  [(size_t)3 * CDIM * CDIM];
__device__ __half g_WgT  [(size_t)CDIM * CDIM];
__device__ __half g_Wp16 [(size_t)CDIM * CDIM];
__device__ __half g_Wf   [(size_t)CDIM * CDIM];
__device__ float  g_bp   [CDIM];
__device__ float  g_bzero[CDIM];
__device__ __half g_biash[(size_t)NH * 64 * 56];   // masked attn bias table (fp16)

// =====================================================================
// helpers
// =====================================================================
__device__ __forceinline__ uint32_t smem_u32(const void* p) {
    uint32_t a;
    asm("{ .reg .u64 t; cvta.to.shared.u64 t, %1; cvt.u32.u64 %0, t; }" : "=r"(a) : "l"(p));
    return a;
}
__device__ __forceinline__ void cp16(uint32_t s, const void* g) {
    asm volatile("cp.async.cg.shared.global [%0], [%1], 16;" :: "r"(s), "l"(g));
}
__device__ __forceinline__ uint32_t pack_h(__half a, __half b) {
    return ((uint32_t)__half_as_ushort(b) << 16) | __half_as_ushort(a);
}
__device__ __forceinline__ uint32_t f2h2(float a, float b) {
    __half2 h = __floats2half2_rn(a, b);
    return *(uint32_t*)&h;
}
#define MMA16816(d, a0, a1, a2, a3, b0, b1)                                   \
    asm volatile(                                                             \
        "mma.sync.aligned.m16n8k16.row.col.f32.f16.f16.f32 "                  \
        "{%0,%1,%2,%3}, {%4,%5,%6,%7}, {%8,%9}, {%0,%1,%2,%3};"               \
        : "+f"((d)[0]), "+f"((d)[1]), "+f"((d)[2]), "+f"((d)[3])              \
        : "r"(a0), "r"(a1), "r"(a2), "r"(a3), "r"(b0), "r"(b1))

// =====================================================================
// merged prep kernel — block-range dispatch
// =====================================================================
#define PB_X    50176
#define PB_BIAS 50400
#define PB_TR   50656
#define PB_CVP  50912
#define PB_CVQ  51680
#define PB_BPR  51744

__device__ __forceinline__ void cvt_body(const float* __restrict__ src,
                                         __half* __restrict__ dst,
                                         int i, int n4)
{
    if (i >= n4) return;
    float4 v = ((const float4*)src)[i];
    uint32_t* p = (uint32_t*)(dst + (size_t)i * 4);
    p[0] = pack_h(__float2half_rn(v.x), __float2half_rn(v.y));
    p[1] = pack_h(__float2half_rn(v.z), __float2half_rn(v.w));
}

__global__ void prep_kernel(const float* __restrict__ x,
                            const float* __restrict__ w_qkv,
                            const float* __restrict__ w_gamma,
                            const float* __restrict__ w_proj,
                            const float* __restrict__ b_gamma,
                            const float* __restrict__ b_proj,
                            const float* __restrict__ bias_table,
                            const int*   __restrict__ rel_idx,
                            __half* __restrict__ X16,
                            __half* __restrict__ W16,
                            __half* __restrict__ WgT,
                            __half* __restrict__ Wp16,
                            float* __restrict__ bp_out,
                            __half* __restrict__ bf)
{
    __shared__ float tile[32][33];
    const int bid = blockIdx.x;
    const int tid = threadIdx.x;

    if (bid < PB_X) {
        cvt_body(x, X16, bid * 256 + tid, (M_TOT * CDIM) / 4);
    } else if (bid < PB_BIAS) {
        const int idx = (bid - PB_X) * 256 + tid;
        if (idx < NH * 64 * 56) {
            const int j = idx % 56;
            const int i = (idx / 56) % 64;
            const int h = idx / (56 * 64);
            float v;
            if (j >= NTOK)      v = -60000.f;   // fp16-representable mask; exp -> 0
            else if (i >= NTOK) v = 0.f;
            else                v = bias_table[rel_idx[i * NTOK + j] * NH + h];
            bf[idx] = __float2half_rn(v);
        }
    } else if (bid < PB_TR) {
        const int blk = bid - PB_BIAS;
        const int bx = (blk & 15) * 32, by = (blk >> 4) * 32;
        const int tx = tid & 31, ty = tid >> 5;     // 32 x 8
#pragma unroll
        for (int i = 0; i < 4; i++)
            tile[ty + 8 * i][tx] = w_gamma[(size_t)(by + ty + 8 * i) * CDIM + bx + tx];
        __syncthreads();
#pragma unroll
        for (int i = 0; i < 4; i++)
            WgT[(size_t)(bx + ty + 8 * i) * CDIM + by + tx] =
                __float2half_rn(tile[tx][ty + 8 * i]);
    } else if (bid < PB_CVP) {
        cvt_body(w_proj, Wp16, (bid - PB_TR) * 256 + tid, (CDIM * CDIM) / 4);
    } else if (bid < PB_CVQ) {
        cvt_body(w_qkv, W16, (bid - PB_CVP) * 256 + tid, (3 * CDIM * CDIM) / 4);
    } else {
        const int warp = (bid - PB_CVQ) * 8 + (tid >> 5);
        const int lane = tid & 31;
        if (warp < CDIM) {
            const float4* Wp4 = (const float4*)(w_proj + (size_t)warp * CDIM);
            const float4* bg4 = (const float4*)b_gamma;
            float s = 0.f;
#pragma unroll
            for (int i = 0; i < 4; i++) {
                const float4 wv = Wp4[lane + 32 * i];
                const float4 bv = bg4[lane + 32 * i];
                s = fmaf(wv.x, bv.x, s); s = fmaf(wv.y, bv.y, s);
                s = fmaf(wv.z, bv.z, s); s = fmaf(wv.w, bv.w, s);
            }
#pragma unroll
            for (int o = 16; o > 0; o >>= 1)
                s += __shfl_xor_sync(0xFFFFFFFF, s, o);
            if (lane == 0) bp_out[warp] = s + b_proj[warp];
        }
    }
}

// =====================================================================
// FP16 GEMM, multi-tile CTAs, continuous 3-stage cp.async pipeline.
// CTA tile 128x128, BK=64, 256 thr, warp tile 64x32.
// qscale: if set, fp16-output columns < 512 are multiplied by 0.25 (Q-prescale).
// =====================================================================
#define BKB 64
#define STAGE_A (128 * BKB * 2)      // 16384
#define STAGE_BYTES (2 * STAGE_A)    // 32768
#define GEMM_SMEM (3 * STAGE_BYTES)  // 98304

__global__ void __launch_bounds__(256)
gemm_fp16(const __half* __restrict__ A,
          const __half* __restrict__ B,
          const float* __restrict__ bias,
          float* __restrict__ Cf,
          __half* __restrict__ Ch,
          int N, int out_mode, int tpc, int qscale)
{
    extern __shared__ char smem[];
    const uint32_t sb = smem_u32(smem);
    const int tid  = threadIdx.x;
    const int lane = tid & 31;
    const int wid  = tid >> 5;
    const int wm   = wid >> 2;
    const int wn   = wid & 3;

    const int mtile0 = blockIdx.y * tpc;
    const int nstep  = tpc * 8;
    const __half* Bg = B + (size_t)blockIdx.x * 128 * KEFF;

    const int lr = tid >> 3;
    const int lc = tid & 7;

    auto load_stage = [&](int step, int slot) {
        if (step >= nstep) return;
        const uint32_t base = sb + (uint32_t)slot * STAGE_BYTES;
        const __half* Ag = A + (size_t)(mtile0 + (step >> 3)) * 128 * KEFF;
        const int kof = (step & 7) * BKB;
#pragma unroll
        for (int i = 0; i < 4; i++) {
            const int r = lr + i * 32;
            const uint32_t so = (uint32_t)r * 128 + (uint32_t)((lc ^ (r & 7)) << 4);
            cp16(base + so,           Ag + (size_t)r * KEFF + kof + lc * 8);
            cp16(base + STAGE_A + so, Bg + (size_t)r * KEFF + kof + lc * 8);
        }
    };

    const int nBase = blockIdx.x * 128 + wn * 32;
    const int rr = lane >> 2;
    const int cc = (lane & 3) * 2;
    float bcx[4], bcy[4], scl[4];
#pragma unroll
    for (int in = 0; in < 4; in++) {
        bcx[in] = bias[nBase + in * 8 + cc];
        bcy[in] = bias[nBase + in * 8 + cc + 1];
        scl[in] = (qscale && (nBase + in * 8) < 512) ? 0.25f : 1.0f;
    }

    float acc[4][4][4];
#pragma unroll
    for (int a = 0; a < 4; a++)
#pragma unroll
        for (int b = 0; b < 4; b++)
#pragma unroll
            for (int c = 0; c < 4; c++) acc[a][b][c] = 0.f;

    load_stage(0, 0); asm volatile("cp.async.commit_group;" ::: "memory");
    load_stage(1, 1); asm volatile("cp.async.commit_group;" ::: "memory");

    const int rA0 = wm * 64 + (lane & 15);
    const int cAh = lane >> 4;
    const int gB  = lane >> 3;
    const int rB0 = wn * 32 + (lane & 7);
    const int rBo = (gB >> 1) * 8;
    const int cBh = gB & 1;

    for (int s = 0; s < nstep; s++) {
        asm volatile("cp.async.wait_group 1;" ::: "memory");
        __syncthreads();
        load_stage(s + 2, (s + 2) % 3);
        asm volatile("cp.async.commit_group;" ::: "memory");

        const uint32_t base = sb + (uint32_t)(s % 3) * STAGE_BYTES;
#pragma unroll
        for (int kk = 0; kk < 4; kk++) {
            uint32_t afr[4][4];
#pragma unroll
            for (int im = 0; im < 4; im++) {
                const int r = rA0 + im * 16;
                const uint32_t addr = base + (uint32_t)r * 128 +
                    (uint32_t)(((2 * kk + cAh) ^ (r & 7)) << 4);
                asm volatile("ldmatrix.sync.aligned.m8n8.x4.shared.b16 {%0,%1,%2,%3}, [%4];"
                    : "=r"(afr[im][0]), "=r"(afr[im][1]), "=r"(afr[im][2]), "=r"(afr[im][3])
                    : "r"(addr));
            }
            uint32_t bfr[4][2];
#pragma unroll
            for (int ip = 0; ip < 2; ip++) {
                const int r = rB0 + ip * 16 + rBo;
                const uint32_t addr = base + STAGE_A + (uint32_t)r * 128 +
                    (uint32_t)(((2 * kk + cBh) ^ (r & 7)) << 4);
                asm volatile("ldmatrix.sync.aligned.m8n8.x4.shared.b16 {%0,%1,%2,%3}, [%4];"
                    : "=r"(bfr[2*ip][0]), "=r"(bfr[2*ip][1]),
                      "=r"(bfr[2*ip+1][0]), "=r"(bfr[2*ip+1][1])
                    : "r"(addr));
            }
#pragma unroll
            for (int im = 0; im < 4; im++)
#pragma unroll
                for (int in = 0; in < 4; in++)
                    MMA16816(acc[im][in], afr[im][0], afr[im][1], afr[im][2], afr[im][3],
                             bfr[in][0], bfr[in][1]);
        }

        if ((s & 7) == 7) {
            const int mBase = (mtile0 + (s >> 3)) * 128 + wm * 64;
            if (!out_mode) {
#pragma unroll
                for (int im = 0; im < 4; im++)
#pragma unroll
                    for (int in = 0; in < 4; in++) {
                        const int row = mBase + im * 16 + rr;
                        const int col = nBase + in * 8 + cc;
                        *(float2*)(Cf + (size_t)row * N + col) =
                            make_float2(acc[im][in][0] + bcx[in], acc[im][in][1] + bcy[in]);
                        *(float2*)(Cf + (size_t)(row + 8) * N + col) =
                            make_float2(acc[im][in][2] + bcx[in], acc[im][in][3] + bcy[in]);
                        acc[im][in][0] = 0.f; acc[im][in][1] = 0.f;
                        acc[im][in][2] = 0.f; acc[im][in][3] = 0.f;
                    }
            } else {
#pragma unroll
                for (int im = 0; im < 4; im++)
#pragma unroll
                    for (int in = 0; in < 4; in++) {
                        const int row = mBase + im * 16 + rr;
                        const int col = nBase + in * 8 + cc;
                        const float sc_ = scl[in];
                        *(uint32_t*)(Ch + (size_t)row * N + col) =
                            pack_h(__float2half_rn((acc[im][in][0] + bcx[in]) * sc_),
                                   __float2half_rn((acc[im][in][1] + bcy[in]) * sc_));
                        *(uint32_t*)(Ch + (size_t)(row + 8) * N + col) =
                            pack_h(__float2half_rn((acc[im][in][2] + bcx[in]) * sc_),
                                   __float2half_rn((acc[im][in][3] + bcy[in]) * sc_));
                        acc[im][in][0] = 0.f; acc[im][in][1] = 0.f;
                        acc[im][in][2] = 0.f; acc[im][in][3] = 0.f;
                    }
            }
        }
    }
}

// =====================================================================
// tensor-core windowed attention (Q pre-scaled; fp16 bias table)
// =====================================================================
#define QOFF  0
#define KOFF  5120
#define VTOFF 10240
#define ATT_HALVES 14848

__global__ void __launch_bounds__(256)
attn_mma_kernel(const __half* __restrict__ qkv,
                const __half* __restrict__ bf,
                __half* __restrict__ outs)
{
    __shared__ __align__(16) __half sm[ATT_HALVES];

    const int b  = blockIdx.x;
    const int h0 = blockIdx.y * 2;
    const int tid = threadIdx.x;
    const uint32_t sb = smem_u32(sm);
    const size_t rowbase = (size_t)b * NTOK;

    {
        uint4 z = make_uint4(0, 0, 0, 0);
        for (int i = tid; i < ATT_HALVES / 8; i += 256)
            ((uint4*)sm)[i] = z;
    }
    __syncthreads();

    for (int it = tid; it < 784; it += 256) {
        const int c   = it & 3;
        const int r3  = it >> 2;
        const int row = r3 % 49;
        const int mh  = r3 / 49;
        const int head = mh & 1;
        const int mat  = mh >> 1;
        const __half* g = qkv + (rowbase + row) * (3 * CDIM) + mat * CDIM + (h0 + head) * HD + c * 8;
        const uint32_t dst = sb + (uint32_t)(mat * KOFF + head * 2560 + row * 40 + c * 8) * 2;
        cp16(dst, g);
    }
    for (int it = tid; it < 1568; it += 256) {
        const int c   = it & 15;
        const int r2  = it >> 4;
        const int row = r2 % 49;
        const int head = r2 / 49;
        const uint32_t v = *(const uint32_t*)(qkv + (rowbase + row) * (3 * CDIM) + 2 * CDIM + (h0 + head) * HD + 2 * c);
        __half* base = sm + VTOFF + head * 2304;
        base[(2 * c) * 72 + row]     = __ushort_as_half((unsigned short)(v & 0xFFFF));
        base[(2 * c + 1) * 72 + row] = __ushort_as_half((unsigned short)(v >> 16));
    }
    asm volatile("cp.async.commit_group;" ::: "memory");
    asm volatile("cp.async.wait_group 0;" ::: "memory");
    __syncthreads();

    const int lane = tid & 31;
    const int wid  = tid >> 5;
    const int head = wid >> 2;
    const int w    = wid & 3;
    const int g    = lane >> 2;
    const int t4   = lane & 3;

    const __half* Q  = sm + QOFF  + head * 2560;
    const __half* K  = sm + KOFF  + head * 2560;
    const __half* Vt = sm + VTOFF + head * 2304;

    float sc[7][4];
#pragma unroll
    for (int n = 0; n < 7; n++)
#pragma unroll
        for (int c = 0; c < 4; c++) sc[n][c] = 0.f;

#pragma unroll
    for (int kh = 0; kh < 2; kh++) {
        const int kc = 16 * kh + 2 * t4;
        const uint32_t a0 = *(const uint32_t*)&Q[(16 * w + g) * 40 + kc];
        const uint32_t a1 = *(const uint32_t*)&Q[(16 * w + g + 8) * 40 + kc];
        const uint32_t a2 = *(const uint32_t*)&Q[(16 * w + g) * 40 + kc + 8];
        const uint32_t a3 = *(const uint32_t*)&Q[(16 * w + g + 8) * 40 + kc + 8];
#pragma unroll
        for (int nt = 0; nt < 7; nt++) {
            const uint32_t b0 = *(const uint32_t*)&K[(8 * nt + g) * 40 + kc];
            const uint32_t b1 = *(const uint32_t*)&K[(8 * nt + g) * 40 + kc + 8];
            MMA16816(sc[nt], a0, a1, a2, a3, b0, b1);
        }
    }

    // ---- + bias (fp16 table), softmax (deferred normalization) ----
    const __half* bfr0 = bf + ((size_t)(h0 + head) * 64 + 16 * w + g) * 56 + 2 * t4;
    const __half* bfr1 = bfr0 + 8 * 56;
    float m0 = -1e30f, m1 = -1e30f;
#pragma unroll
    for (int nt = 0; nt < 7; nt++) {
        const float2 bb0 = __half22float2(*(const __half2*)&bfr0[8 * nt]);
        const float2 bb1 = __half22float2(*(const __half2*)&bfr1[8 * nt]);
        sc[nt][0] += bb0.x;
        sc[nt][1] += bb0.y;
        sc[nt][2] += bb1.x;
        sc[nt][3] += bb1.y;
        m0 = fmaxf(m0, fmaxf(sc[nt][0], sc[nt][1]));
        m1 = fmaxf(m1, fmaxf(sc[nt][2], sc[nt][3]));
    }
    m0 = fmaxf(m0, __shfl_xor_sync(0xFFFFFFFF, m0, 1));
    m0 = fmaxf(m0, __shfl_xor_sync(0xFFFFFFFF, m0, 2));
    m1 = fmaxf(m1, __shfl_xor_sync(0xFFFFFFFF, m1, 1));
    m1 = fmaxf(m1, __shfl_xor_sync(0xFFFFFFFF, m1, 2));

    float s0 = 0.f, s1 = 0.f;
#pragma unroll
    for (int nt = 0; nt < 7; nt++) {
        sc[nt][0] = __expf(sc[nt][0] - m0); s0 += sc[nt][0];
        sc[nt][1] = __expf(sc[nt][1] - m0); s0 += sc[nt][1];
        sc[nt][2] = __expf(sc[nt][2] - m1); s1 += sc[nt][2];
        sc[nt][3] = __expf(sc[nt][3] - m1); s1 += sc[nt][3];
    }
    s0 += __shfl_xor_sync(0xFFFFFFFF, s0, 1);
    s0 += __shfl_xor_sync(0xFFFFFFFF, s0, 2);
    s1 += __shfl_xor_sync(0xFFFFFFFF, s1, 1);
    s1 += __shfl_xor_sync(0xFFFFFFFF, s1, 2);
    const float inv0 = 1.f / s0;
    const float inv1 = 1.f / s1;

    float oa[4][4];
#pragma unroll
    for (int n = 0; n < 4; n++)
#pragma unroll
        for (int c = 0; c < 4; c++) oa[n][c] = 0.f;

#pragma unroll
    for (int kt = 0; kt < 4; kt++) {
        const int n0 = 2 * kt, n1 = 2 * kt + 1;
        const uint32_t a0 = f2h2(sc[n0][0], sc[n0][1]);
        const uint32_t a1 = f2h2(sc[n0][2], sc[n0][3]);
        const uint32_t a2 = (n1 < 7) ? f2h2(sc[n1][0], sc[n1][1]) : 0u;
        const uint32_t a3 = (n1 < 7) ? f2h2(sc[n1][2], sc[n1][3]) : 0u;
        const int jc = 16 * kt + 2 * t4;
#pragma unroll
        for (int nt = 0; nt < 4; nt++) {
            const uint32_t b0 = *(const uint32_t*)&Vt[(8 * nt + g) * 72 + jc];
            const uint32_t b1 = *(const uint32_t*)&Vt[(8 * nt + g) * 72 + jc + 8];
            MMA16816(oa[nt], a0, a1, a2, a3, b0, b1);
        }
    }

    const int i0 = 16 * w + g, i1 = i0 + 8;
    const int dc = 2 * t4;
#pragma unroll
    for (int nt = 0; nt < 4; nt++) {
        const int d = 8 * nt + dc;
        if (i0 < NTOK)
            *(uint32_t*)(outs + (rowbase + i0) * CDIM + (h0 + head) * HD + d) =
                f2h2(oa[nt][0] * inv0, oa[nt][1] * inv0);
        if (i1 < NTOK)
            *(uint32_t*)(outs + (rowbase + i1) * CDIM + (h0 + head) * HD + d) =
                f2h2(oa[nt][2] * inv1, oa[nt][3] * inv1);
    }
}

// =====================================================================
// launch
// =====================================================================
extern "C" void kernel_launch(void* const* d_in, const int* in_sizes, int n_in,
                              void* d_out, int out_size)
{
    const float* x          = (const float*)d_in[0];
    const float* w_qkv      = (const float*)d_in[1];
    const float* b_qkv      = (const float*)d_in[2];
    const float* w_gamma    = (const float*)d_in[3];
    const float* b_gamma    = (const float*)d_in[4];
    const float* w_proj     = (const float*)d_in[5];
    const float* b_proj     = (const float*)d_in[6];
    const float* bias_table = (const float*)d_in[7];
    const int*   rel_idx    = (const int*)d_in[8];
    float* out = (float*)d_out;

    __half *X16, *QKV16, *ATT16, *W16, *WgT, *Wp16, *Wf, *BF;
    float *BP, *BZ;
    cudaGetSymbolAddress((void**)&X16,   g_x16);
    cudaGetSymbolAddress((void**)&QKV16, g_qkv16);
    cudaGetSymbolAddress((void**)&ATT16, g_att16);
    cudaGetSymbolAddress((void**)&W16,   g_W16);
    cudaGetSymbolAddress((void**)&WgT,   g_WgT);
    cudaGetSymbolAddress((void**)&Wp16,  g_Wp16);
    cudaGetSymbolAddress((void**)&Wf,    g_Wf);
    cudaGetSymbolAddress((void**)&BF,    g_biash);
    cudaGetSymbolAddress((void**)&BP,    g_bp);
    cudaGetSymbolAddress((void**)&BZ,    g_bzero);

    cudaFuncSetAttribute(gemm_fp16, cudaFuncAttributeMaxDynamicSharedMemorySize, GEMM_SMEM);

    // 0) merged preps
    prep_kernel<<<PB_BPR, 256>>>(x, w_qkv, w_gamma, w_proj, b_gamma, b_proj,
                                 bias_table, rel_idx,
                                 X16, W16, WgT, Wp16, BP, BF);

    // 0b) W'[512,512] = Wp @ Wg
    {
        dim3 grid(CDIM / 128, 4);
        gemm_fp16<<<grid, 256, GEMM_SMEM>>>(Wp16, WgT, BZ, nullptr, Wf, CDIM, 1, 1, 0);
    }

    // 1) qkv = x @ w_qkv^T + b_qkv (Q cols pre-scaled by 0.25) -> fp16
    {
        dim3 grid(3 * CDIM / 128, M_TOT / 128 / 8);    // 12 x 98
        gemm_fp16<<<grid, 256, GEMM_SMEM>>>(X16, W16, b_qkv, nullptr, QKV16, 3 * CDIM, 1, 8, 1);
    }
    // 2) tensor-core attention -> ATT16 fp16
    {
        dim3 grid(BATCH, NH / 2);
        attn_mma_kernel<<<grid, 256>>>(QKV16, BF, ATT16);
    }
    // 3) out = att @ W'^T + b'  -> fp32 d_out (gamma+proj fused)
    {
        dim3 grid(CDIM / 128, M_TOT / 128 / 4);        // 4 x 196 (wave-balanced)
        gemm_fp16<<<grid, 256, GEMM_SMEM>>>(ATT16, Wf, BP, out, nullptr, CDIM, 0, 4, 0);
    }
}